// round 1
// baseline (speedup 1.0000x reference)
#include <cuda_runtime.h>
#include <cuda_bf16.h>
#include <math.h>

// Problem constants
#define H_DIM   1024
#define M_DIM   64
#define R_DIM   2
#define LS_DIM  2048
#define BATCH   4
#define SEQ     2048
#define NTOK    (BATCH * SEQ)      // 8192
#define PROJ_W  384                // k(128) | v(128) | ql(64) | qr(64)

// Scratch (device globals: allocation-free rule)
__device__ float g_proj[(size_t)NTOK * PROJ_W];    // 12.6 MB
__device__ float g_decay[NTOK];
__device__ float g_ug[(size_t)NTOK * 4096];        // 134 MB: [up(2048) | gate(2048)], up slot reused for t
__device__ float g_sr[(size_t)NTOK * M_DIM];       // silu(reads)

// ---------------------------------------------------------------------------
// Generic fp32 SGEMM: C[M x N] = A[M x K] @ B[K x N]  (row-major, strided)
// BM=128, BN=64, BK=8, TM=8, TN=4, 256 threads.
// Requires: M % 128 == 0, N % 64 == 0, K % 8 == 0 (true for every call here).
// ---------------------------------------------------------------------------
template <bool ACC>
__global__ __launch_bounds__(256) void sgemm_kernel(
    const float* __restrict__ A, const float* __restrict__ B, float* __restrict__ C,
    int K, int lda, int ldb, int ldc)
{
    constexpr int BM = 128, BN = 64, BK = 8, TM = 8, TN = 4;
    __shared__ float As[BK][BM];   // transposed A tile
    __shared__ float Bs[BK][BN];

    const int tid = threadIdx.x;
    const int bm = blockIdx.y * BM;
    const int bn = blockIdx.x * BN;

    const int tr = tid >> 4;          // 0..15 : row group (TM rows)
    const int tc = tid & 15;          // 0..15 : col group (TN cols)

    const int aRow = tid >> 1;            // 0..127
    const int aCol = (tid & 1) * 4;       // 0 or 4
    const int bRow = tid >> 4;            // 0..7 (only tid<128 loads B)
    const int bCol = (tid & 15) * 4;

    float acc[TM][TN];
#pragma unroll
    for (int i = 0; i < TM; ++i)
#pragma unroll
        for (int j = 0; j < TN; ++j) acc[i][j] = 0.0f;

    const float* Ab = A + (long)bm * lda;
    const float* Bb = B + bn;

    for (int k0 = 0; k0 < K; k0 += BK) {
        float4 av = *(const float4*)(Ab + (long)aRow * lda + k0 + aCol);
        As[aCol + 0][aRow] = av.x;
        As[aCol + 1][aRow] = av.y;
        As[aCol + 2][aRow] = av.z;
        As[aCol + 3][aRow] = av.w;
        if (tid < 128) {
            float4 bv = *(const float4*)(Bb + (long)(k0 + bRow) * ldb + bCol);
            *(float4*)&Bs[bRow][bCol] = bv;
        }
        __syncthreads();

#pragma unroll
        for (int k = 0; k < BK; ++k) {
            float ra[TM], rb[TN];
            *(float4*)&ra[0] = *(const float4*)&As[k][tr * TM];
            *(float4*)&ra[4] = *(const float4*)&As[k][tr * TM + 4];
            *(float4*)&rb[0] = *(const float4*)&Bs[k][tc * TN];
#pragma unroll
            for (int i = 0; i < TM; ++i)
#pragma unroll
                for (int j = 0; j < TN; ++j)
                    acc[i][j] = fmaf(ra[i], rb[j], acc[i][j]);
        }
        __syncthreads();
    }

#pragma unroll
    for (int i = 0; i < TM; ++i) {
        float* cp = C + (long)(bm + tr * TM + i) * ldc + bn + tc * TN;
#pragma unroll
        for (int j = 0; j < TN; ++j) {
            if (ACC) cp[j] += acc[i][j];
            else     cp[j]  = acc[i][j];
        }
    }
}

// ---------------------------------------------------------------------------
// decay[t] = sigmoid(x[t,:] . W_decay)  — one warp per token
// ---------------------------------------------------------------------------
__global__ __launch_bounds__(256) void decay_kernel(
    const float* __restrict__ x, const float* __restrict__ Wd, float* __restrict__ dec)
{
    const int token = blockIdx.x * 8 + (threadIdx.x >> 5);
    const int lane = threadIdx.x & 31;
    const float* xr = x + (long)token * H_DIM;
    float s = 0.0f;
#pragma unroll 8
    for (int j = lane; j < H_DIM; j += 32) s = fmaf(xr[j], Wd[j], s);
#pragma unroll
    for (int o = 16; o; o >>= 1) s += __shfl_xor_sync(0xffffffffu, s, o);
    if (lane == 0) dec[token] = 1.0f / (1.0f + expf(-s));
}

// ---------------------------------------------------------------------------
// t = up * silu(gate), written in place into the up slot of g_ug
// ---------------------------------------------------------------------------
__global__ __launch_bounds__(256) void swiglu_kernel(float* __restrict__ ug)
{
    long i = (long)blockIdx.x * blockDim.x + threadIdx.x;   // over NTOK*2048
    long row = i >> 11;
    int  c = (int)(i & 2047);
    float* p = ug + (row << 12);
    float up = p[c];
    float g  = p[2048 + c];
    p[c] = up * (g / (1.0f + expf(-g)));
}

// ---------------------------------------------------------------------------
// Sequential scan. Grid (8, B): 8 n-groups of NC=8 columns per batch.
// 512 threads: tid = nl*64 + m  (nl: local n, m: state row).
// Each thread carries st = state[m, n] in a register.
// Recurrence chain is elementwise (no reduction in the loop-carried dep);
// the read reduction (over m) happens off the chain via warp shuffles.
// Next-step inputs are prefetched to hide L2 latency. One barrier per step
// (double-buffered shared partials).
// ---------------------------------------------------------------------------
__global__ __launch_bounds__(512) void scan_kernel(
    const float* __restrict__ proj, const float* __restrict__ decay,
    const float* __restrict__ init_state, float* __restrict__ sr)
{
    const int b   = blockIdx.y;
    const int n0  = blockIdx.x * 8;
    const int tid = threadIdx.x;
    const int nl  = tid >> 6;          // 0..7
    const int m   = tid & 63;
    const int n   = n0 + nl;
    const int lane = tid & 31;
    const int half = (m >> 5);

    __shared__ float part[2][8][2];

    float st = init_state[m * M_DIM + n];
    const long base = (long)b * SEQ;

    // preload step 0
    const float* row = proj + (base + 0) * PROJ_W;
    float d   = decay[base];
    float k0  = row[m],        k1  = row[64 + m];
    float v0  = row[128 + n],  v1  = row[192 + n];
    float qlm = row[256 + m],  qrn = row[320 + n];

    for (int s = 0; s < SEQ; ++s) {
        float nd = 0.f, nk0 = 0.f, nk1 = 0.f, nv0 = 0.f, nv1 = 0.f, nql = 0.f, nqr = 0.f;
        if (s + 1 < SEQ) {
            const float* nr = proj + (base + s + 1) * PROJ_W;
            nd  = decay[base + s + 1];
            nk0 = nr[m];        nk1 = nr[64 + m];
            nv0 = nr[128 + n];  nv1 = nr[192 + n];
            nql = nr[256 + m];  nqr = nr[320 + n];
        }

        // state = d*state + (1-d)*write,  write = (k0 v0 + k1 v1)/R
        float w = 0.5f * (k0 * v0 + k1 * v1);
        st = fmaf(d, st, (1.0f - d) * w);

        // read[n] = (sum_m ql[m] * st[m,n]) * qr[n]
        float p = qlm * st;
#pragma unroll
        for (int o = 16; o; o >>= 1) p += __shfl_xor_sync(0xffffffffu, p, o);
        if (lane == 0) part[s & 1][nl][half] = p;
        __syncthreads();
        if (m == 0) {
            float rd = (part[s & 1][nl][0] + part[s & 1][nl][1]) * qrn;
            sr[(base + s) * M_DIM + n] = rd / (1.0f + expf(-rd));   // silu
        }

        d = nd; k0 = nk0; k1 = nk1; v0 = nv0; v1 = nv1; qlm = nql; qrn = nqr;
    }
}

// ---------------------------------------------------------------------------
extern "C" void kernel_launch(void* const* d_in, const int* in_sizes, int n_in,
                              void* d_out, int out_size)
{
    const float* x       = (const float*)d_in[0];
    const float* W_decay = (const float*)d_in[1];
    const float* W_key   = (const float*)d_in[2];
    const float* W_value = (const float*)d_in[3];
    const float* W_ql    = (const float*)d_in[4];
    const float* W_qr    = (const float*)d_in[5];
    const float* W_rec   = (const float*)d_in[6];
    const float* W_up    = (const float*)d_in[7];
    const float* W_gate  = (const float*)d_in[8];
    const float* W_down  = (const float*)d_in[9];
    const float* init_st = (const float*)d_in[10];
    float* out = (float*)d_out;

    void *p_proj, *p_dec, *p_ug, *p_sr;
    cudaGetSymbolAddress(&p_proj, g_proj);
    cudaGetSymbolAddress(&p_dec,  g_decay);
    cudaGetSymbolAddress(&p_ug,   g_ug);
    cudaGetSymbolAddress(&p_sr,   g_sr);
    float* proj = (float*)p_proj;
    float* dec  = (float*)p_dec;
    float* ug   = (float*)p_ug;
    float* sr   = (float*)p_sr;

    const dim3 blk(256);
    const int MB = NTOK / 128;   // 64 row-blocks

    // Small projections: k, v, ql, qr  -> g_proj rows [k|v|ql|qr]
    sgemm_kernel<false><<<dim3(2, MB), blk>>>(x, W_key,   proj + 0,   H_DIM, H_DIM, 128,  PROJ_W);
    sgemm_kernel<false><<<dim3(2, MB), blk>>>(x, W_value, proj + 128, H_DIM, H_DIM, 128,  PROJ_W);
    sgemm_kernel<false><<<dim3(1, MB), blk>>>(x, W_ql,    proj + 256, H_DIM, H_DIM, 64,   PROJ_W);
    sgemm_kernel<false><<<dim3(1, MB), blk>>>(x, W_qr,    proj + 320, H_DIM, H_DIM, 64,   PROJ_W);

    // decay
    decay_kernel<<<NTOK / 8, blk>>>(x, W_decay, dec);

    // FFN: up, gate -> g_ug ; t = up*silu(gate) in place
    sgemm_kernel<false><<<dim3(32, MB), blk>>>(x, W_up,   ug + 0,    H_DIM, H_DIM, LS_DIM, 4096);
    sgemm_kernel<false><<<dim3(32, MB), blk>>>(x, W_gate, ug + 2048, H_DIM, H_DIM, LS_DIM, 4096);
    swiglu_kernel<<<(NTOK * 2048) / 256, blk>>>(ug);

    // Sequential recurrence -> silu(reads)
    scan_kernel<<<dim3(8, BATCH), dim3(512)>>>(proj, dec, init_st, sr);

    // out = t @ W_down
    sgemm_kernel<false><<<dim3(16, MB), blk>>>(ug, W_down, out, LS_DIM, 4096, H_DIM, H_DIM);
    // out += silu(reads) @ W_rec_out
    sgemm_kernel<true><<<dim3(16, MB), blk>>>(sr, W_rec, out, M_DIM, M_DIM, H_DIM, H_DIM);
}

// round 2
// speedup vs baseline: 2.0263x; 2.0263x over previous
#include <cuda_runtime.h>
#include <cuda_bf16.h>
#include <math.h>
#include <stdint.h>

// Problem constants
#define H_DIM   1024
#define M_DIM   64
#define LS_DIM  2048
#define BATCH   4
#define SEQ     2048
#define NTOK    (BATCH * SEQ)      // 8192
#define PROJ_W  384                // k(128) | v(128) | ql(64) | qr(64)

// Scratch (device globals: allocation-free rule)
__device__ float g_proj[(size_t)NTOK * PROJ_W];
__device__ float g_decay[NTOK];
__device__ float g_ug[(size_t)NTOK * 4096];        // [up(2048)|gate(2048)]; up slot reused for t
__device__ float g_sr[(size_t)NTOK * M_DIM];       // silu(reads)
__device__ float g_wproj[(size_t)H_DIM * PROJ_W];  // packed [Wk|Wv|Wql|Wqr]
__device__ float g_wug[(size_t)H_DIM * 4096];      // packed [Wup|Wgate]

// ---------------------------------------------------------------------------
// tf32 helpers
// ---------------------------------------------------------------------------
__device__ __forceinline__ float to_tf32(float x) {
    float r;
    asm("cvt.rna.tf32.f32 %0, %1;" : "=f"(r) : "f"(x));
    return r;
}

__device__ __forceinline__ void mma_tf32(float* c, const uint32_t* a, const uint32_t* b) {
    asm volatile(
        "mma.sync.aligned.m16n8k8.row.col.f32.tf32.tf32.f32 "
        "{%0,%1,%2,%3}, {%4,%5,%6,%7}, {%8,%9}, {%0,%1,%2,%3};"
        : "+f"(c[0]), "+f"(c[1]), "+f"(c[2]), "+f"(c[3])
        : "r"(a[0]), "r"(a[1]), "r"(a[2]), "r"(a[3]), "r"(b[0]), "r"(b[1]));
}

// ---------------------------------------------------------------------------
// tf32 tensor-core GEMM: C[M x N] = A[M x K] @ B[K x N] (row-major, strided)
// BM=BN=128, BK=16, 256 threads (8 warps, 4x2 warp grid, 32x64 warp tile).
// Double-buffered smem, 136-float row stride (conflict-free frag loads).
// Requires M%128==0, N%128==0, K%16==0.
// ---------------------------------------------------------------------------
template <bool ACC>
__global__ __launch_bounds__(256) void tf32_gemm(
    const float* __restrict__ A, const float* __restrict__ B, float* __restrict__ C,
    int K, int lda, int ldb, int ldc)
{
    constexpr int BM = 128, BN = 128, BK = 16, LDS_ = 136;
    __shared__ float As[2][BK][LDS_];
    __shared__ float Bs[2][BK][LDS_];

    const int tid = threadIdx.x;
    const int bm = blockIdx.y * BM;
    const int bn = blockIdx.x * BN;

    const int w    = tid >> 5;
    const int lane = tid & 31;
    const int wm = (w & 3) * 32;       // warp row offset
    const int wn = (w >> 2) * 64;      // warp col offset
    const int g  = lane >> 2;          // 0..7
    const int tg = lane & 3;           // 0..3

    // A staging: thread covers rows (ar, ar+64), k-cols [aq, aq+4)
    const int ar = tid >> 2;
    const int aq = (tid & 3) * 4;
    const float* Ap0 = A + (long)(bm + ar) * lda + aq;
    const float* Ap1 = A + (long)(bm + ar + 64) * lda + aq;
    // B staging: thread covers k-rows (bk, bk+8), cols [bc, bc+4)
    const int bk = tid >> 5;
    const int bc = (tid & 31) * 4;
    const float* Bp0 = B + (long)bk * ldb + bn + bc;
    const float* Bp1 = B + (long)(bk + 8) * ldb + bn + bc;

    float acc[2][8][4];
#pragma unroll
    for (int i = 0; i < 2; ++i)
#pragma unroll
        for (int j = 0; j < 8; ++j)
#pragma unroll
            for (int q = 0; q < 4; ++q) acc[i][j][q] = 0.0f;

    const int ntile = K / BK;

    // prologue: tile 0 -> buf 0
    {
        float4 a0 = *(const float4*)Ap0;
        float4 a1 = *(const float4*)Ap1;
        float4 b0 = *(const float4*)Bp0;
        float4 b1 = *(const float4*)Bp1;
        As[0][aq + 0][ar] = to_tf32(a0.x);
        As[0][aq + 1][ar] = to_tf32(a0.y);
        As[0][aq + 2][ar] = to_tf32(a0.z);
        As[0][aq + 3][ar] = to_tf32(a0.w);
        As[0][aq + 0][ar + 64] = to_tf32(a1.x);
        As[0][aq + 1][ar + 64] = to_tf32(a1.y);
        As[0][aq + 2][ar + 64] = to_tf32(a1.z);
        As[0][aq + 3][ar + 64] = to_tf32(a1.w);
        float4 t0 = make_float4(to_tf32(b0.x), to_tf32(b0.y), to_tf32(b0.z), to_tf32(b0.w));
        float4 t1 = make_float4(to_tf32(b1.x), to_tf32(b1.y), to_tf32(b1.z), to_tf32(b1.w));
        *(float4*)&Bs[0][bk][bc]     = t0;
        *(float4*)&Bs[0][bk + 8][bc] = t1;
    }
    __syncthreads();

    int buf = 0;
    for (int t = 0; t < ntile; ++t) {
        float4 a0, a1, b0, b1;
        const bool pf = (t + 1 < ntile);
        if (pf) {
            const int ko = (t + 1) * BK;
            a0 = *(const float4*)(Ap0 + ko);
            a1 = *(const float4*)(Ap1 + ko);
            b0 = *(const float4*)(Bp0 + (long)ko * ldb);
            b1 = *(const float4*)(Bp1 + (long)ko * ldb);
        }

        // compute on smem[buf]
#pragma unroll
        for (int kk = 0; kk < BK; kk += 8) {
            uint32_t af[2][4];
#pragma unroll
            for (int i = 0; i < 2; ++i) {
                const int mo = wm + i * 16;
                af[i][0] = __float_as_uint(As[buf][kk + tg][mo + g]);
                af[i][1] = __float_as_uint(As[buf][kk + tg][mo + g + 8]);
                af[i][2] = __float_as_uint(As[buf][kk + tg + 4][mo + g]);
                af[i][3] = __float_as_uint(As[buf][kk + tg + 4][mo + g + 8]);
            }
#pragma unroll
            for (int j = 0; j < 8; ++j) {
                uint32_t bf[2];
                bf[0] = __float_as_uint(Bs[buf][kk + tg][wn + j * 8 + g]);
                bf[1] = __float_as_uint(Bs[buf][kk + tg + 4][wn + j * 8 + g]);
                mma_tf32(acc[0][j], af[0], bf);
                mma_tf32(acc[1][j], af[1], bf);
            }
        }

        if (pf) {
            const int nb = buf ^ 1;
            As[nb][aq + 0][ar] = to_tf32(a0.x);
            As[nb][aq + 1][ar] = to_tf32(a0.y);
            As[nb][aq + 2][ar] = to_tf32(a0.z);
            As[nb][aq + 3][ar] = to_tf32(a0.w);
            As[nb][aq + 0][ar + 64] = to_tf32(a1.x);
            As[nb][aq + 1][ar + 64] = to_tf32(a1.y);
            As[nb][aq + 2][ar + 64] = to_tf32(a1.z);
            As[nb][aq + 3][ar + 64] = to_tf32(a1.w);
            float4 t0 = make_float4(to_tf32(b0.x), to_tf32(b0.y), to_tf32(b0.z), to_tf32(b0.w));
            float4 t1 = make_float4(to_tf32(b1.x), to_tf32(b1.y), to_tf32(b1.z), to_tf32(b1.w));
            *(float4*)&Bs[nb][bk][bc]     = t0;
            *(float4*)&Bs[nb][bk + 8][bc] = t1;
        }
        __syncthreads();
        buf ^= 1;
    }

    // writeback: c0,c1 -> row g, cols 2tg,2tg+1 ; c2,c3 -> row g+8
#pragma unroll
    for (int i = 0; i < 2; ++i) {
        const int row0 = bm + wm + i * 16 + g;
#pragma unroll
        for (int j = 0; j < 8; ++j) {
            const int col = bn + wn + j * 8 + tg * 2;
            float* p0 = C + (long)row0 * ldc + col;
            float* p1 = p0 + 8 * ldc;
            if (ACC) {
                p0[0] += acc[i][j][0]; p0[1] += acc[i][j][1];
                p1[0] += acc[i][j][2]; p1[1] += acc[i][j][3];
            } else {
                p0[0] = acc[i][j][0]; p0[1] = acc[i][j][1];
                p1[0] = acc[i][j][2]; p1[1] = acc[i][j][3];
            }
        }
    }
}

// ---------------------------------------------------------------------------
// Weight packing
// ---------------------------------------------------------------------------
__global__ __launch_bounds__(256) void pack_proj_kernel(
    const float* __restrict__ Wk, const float* __restrict__ Wv,
    const float* __restrict__ Wql, const float* __restrict__ Wqr,
    float* __restrict__ P)
{
    int i = blockIdx.x * 256 + threadIdx.x;     // over H_DIM * 384
    int r = i / PROJ_W, c = i % PROJ_W;
    float v;
    if (c < 128)      v = Wk[r * 128 + c];
    else if (c < 256) v = Wv[r * 128 + (c - 128)];
    else if (c < 320) v = Wql[r * 64 + (c - 256)];
    else              v = Wqr[r * 64 + (c - 320)];
    P[i] = v;
}

__global__ __launch_bounds__(256) void pack_ug_kernel(
    const float* __restrict__ Wu, const float* __restrict__ Wg, float* __restrict__ P)
{
    int i = blockIdx.x * 256 + threadIdx.x;     // over H_DIM * 4096
    int r = i >> 12, c = i & 4095;
    P[i] = (c < 2048) ? Wu[r * 2048 + c] : Wg[r * 2048 + (c - 2048)];
}

// ---------------------------------------------------------------------------
// decay[t] = sigmoid(x[t,:] . W_decay)  — one warp per token
// ---------------------------------------------------------------------------
__global__ __launch_bounds__(256) void decay_kernel(
    const float* __restrict__ x, const float* __restrict__ Wd, float* __restrict__ dec)
{
    const int token = blockIdx.x * 8 + (threadIdx.x >> 5);
    const int lane = threadIdx.x & 31;
    const float* xr = x + (long)token * H_DIM;
    float s = 0.0f;
#pragma unroll 8
    for (int j = lane; j < H_DIM; j += 32) s = fmaf(xr[j], Wd[j], s);
#pragma unroll
    for (int o = 16; o; o >>= 1) s += __shfl_xor_sync(0xffffffffu, s, o);
    if (lane == 0) dec[token] = 1.0f / (1.0f + expf(-s));
}

// ---------------------------------------------------------------------------
// t = up * silu(gate), in place into the up slot of g_ug
// ---------------------------------------------------------------------------
__global__ __launch_bounds__(256) void swiglu_kernel(float* __restrict__ ug)
{
    long i = (long)blockIdx.x * blockDim.x + threadIdx.x;   // over NTOK*2048
    long row = i >> 11;
    int  c = (int)(i & 2047);
    float* p = ug + (row << 12);
    float up = p[c];
    float gt = p[2048 + c];
    p[c] = up * (gt / (1.0f + expf(-gt)));
}

// ---------------------------------------------------------------------------
// Sequential scan (see round-1 comments). Grid (8, B), 512 threads.
// ---------------------------------------------------------------------------
__global__ __launch_bounds__(512) void scan_kernel(
    const float* __restrict__ proj, const float* __restrict__ decay,
    const float* __restrict__ init_state, float* __restrict__ sr)
{
    const int b   = blockIdx.y;
    const int n0  = blockIdx.x * 8;
    const int tid = threadIdx.x;
    const int nl  = tid >> 6;
    const int m   = tid & 63;
    const int n   = n0 + nl;
    const int lane = tid & 31;
    const int half = (m >> 5);

    __shared__ float part[2][8][2];

    float st = init_state[m * M_DIM + n];
    const long base = (long)b * SEQ;

    const float* row = proj + (base + 0) * PROJ_W;
    float d   = decay[base];
    float k0  = row[m],        k1  = row[64 + m];
    float v0  = row[128 + n],  v1  = row[192 + n];
    float qlm = row[256 + m],  qrn = row[320 + n];

    for (int s = 0; s < SEQ; ++s) {
        float nd = 0.f, nk0 = 0.f, nk1 = 0.f, nv0 = 0.f, nv1 = 0.f, nql = 0.f, nqr = 0.f;
        if (s + 1 < SEQ) {
            const float* nr = proj + (base + s + 1) * PROJ_W;
            nd  = decay[base + s + 1];
            nk0 = nr[m];        nk1 = nr[64 + m];
            nv0 = nr[128 + n];  nv1 = nr[192 + n];
            nql = nr[256 + m];  nqr = nr[320 + n];
        }

        float wv = 0.5f * (k0 * v0 + k1 * v1);
        st = fmaf(d, st, (1.0f - d) * wv);

        float p = qlm * st;
#pragma unroll
        for (int o = 16; o; o >>= 1) p += __shfl_xor_sync(0xffffffffu, p, o);
        if (lane == 0) part[s & 1][nl][half] = p;
        __syncthreads();
        if (m == 0) {
            float rd = (part[s & 1][nl][0] + part[s & 1][nl][1]) * qrn;
            sr[(base + s) * M_DIM + n] = rd / (1.0f + expf(-rd));
        }

        d = nd; k0 = nk0; k1 = nk1; v0 = nv0; v1 = nv1; qlm = nql; qrn = nqr;
    }
}

// ---------------------------------------------------------------------------
extern "C" void kernel_launch(void* const* d_in, const int* in_sizes, int n_in,
                              void* d_out, int out_size)
{
    const float* x       = (const float*)d_in[0];
    const float* W_decay = (const float*)d_in[1];
    const float* W_key   = (const float*)d_in[2];
    const float* W_value = (const float*)d_in[3];
    const float* W_ql    = (const float*)d_in[4];
    const float* W_qr    = (const float*)d_in[5];
    const float* W_rec   = (const float*)d_in[6];
    const float* W_up    = (const float*)d_in[7];
    const float* W_gate  = (const float*)d_in[8];
    const float* W_down  = (const float*)d_in[9];
    const float* init_st = (const float*)d_in[10];
    float* out = (float*)d_out;

    void *p_proj, *p_dec, *p_ug, *p_sr, *p_wp, *p_wug;
    cudaGetSymbolAddress(&p_proj, g_proj);
    cudaGetSymbolAddress(&p_dec,  g_decay);
    cudaGetSymbolAddress(&p_ug,   g_ug);
    cudaGetSymbolAddress(&p_sr,   g_sr);
    cudaGetSymbolAddress(&p_wp,   g_wproj);
    cudaGetSymbolAddress(&p_wug,  g_wug);
    float* proj = (float*)p_proj;
    float* dec  = (float*)p_dec;
    float* ug   = (float*)p_ug;
    float* sr   = (float*)p_sr;
    float* wp   = (float*)p_wp;
    float* wug  = (float*)p_wug;

    const dim3 blk(256);
    const int MB = NTOK / 128;   // 64 row-blocks

    // Pack weights
    pack_proj_kernel<<<(H_DIM * PROJ_W) / 256, blk>>>(W_key, W_value, W_ql, W_qr, wp);
    pack_ug_kernel<<<(H_DIM * 4096) / 256, blk>>>(W_up, W_gate, wug);

    // decay (independent of packs)
    decay_kernel<<<NTOK / 8, blk>>>(x, W_decay, dec);

    // Projections: one GEMM, N=384
    tf32_gemm<false><<<dim3(3, MB), blk>>>(x, wp, proj, H_DIM, H_DIM, PROJ_W, PROJ_W);

    // FFN up|gate: one GEMM, N=4096
    tf32_gemm<false><<<dim3(32, MB), blk>>>(x, wug, ug, H_DIM, H_DIM, 4096, 4096);
    swiglu_kernel<<<(NTOK * 2048) / 256, blk>>>(ug);

    // Sequential recurrence -> silu(reads)
    scan_kernel<<<dim3(8, BATCH), dim3(512)>>>(proj, dec, init_st, sr);

    // out = t @ W_down
    tf32_gemm<false><<<dim3(8, MB), blk>>>(ug, W_down, out, LS_DIM, 4096, H_DIM, H_DIM);
    // out += silu(reads) @ W_rec_out
    tf32_gemm<true><<<dim3(8, MB), blk>>>(sr, W_rec, out, M_DIM, M_DIM, H_DIM, H_DIM);
}

// round 3
// speedup vs baseline: 2.6957x; 1.3304x over previous
#include <cuda_runtime.h>
#include <cuda_bf16.h>
#include <math.h>
#include <stdint.h>

// Problem constants
#define H_DIM   1024
#define M_DIM   64
#define LS_DIM  2048
#define BATCH   4
#define SEQ     2048
#define NTOK    (BATCH * SEQ)      // 8192
#define PROJ_W  384                // k(128) | v(128) | ql(64) | qr(64)
#define CHUNK   64
#define NCHUNK  (SEQ / CHUNK)      // 32

// Scratch (device globals: allocation-free rule)
__device__ float g_proj[(size_t)NTOK * PROJ_W];
__device__ float g_decay[NTOK];
__device__ float g_t[(size_t)NTOK * LS_DIM];        // fused up*silu(gate)
__device__ float g_sr[(size_t)NTOK * M_DIM];        // silu(reads)
__device__ float g_wproj[(size_t)H_DIM * PROJ_W];   // packed [Wk|Wv|Wql|Wqr]
__device__ float g_wug[(size_t)H_DIM * 4096];       // packed interleaved [u64|g64]x32
__device__ float g_cA[BATCH * NCHUNK];              // per-chunk decay product
__device__ float g_cB[(size_t)BATCH * NCHUNK * 4096]; // per-chunk write accum (64x64)
__device__ float g_cS[(size_t)BATCH * NCHUNK * 4096]; // chunk-start states

// ---------------------------------------------------------------------------
__device__ __forceinline__ float to_tf32(float x) {
    float r;
    asm("cvt.rna.tf32.f32 %0, %1;" : "=f"(r) : "f"(x));
    return r;
}
__device__ __forceinline__ void mma_tf32(float* c, const uint32_t* a, const uint32_t* b) {
    asm volatile(
        "mma.sync.aligned.m16n8k8.row.col.f32.tf32.tf32.f32 "
        "{%0,%1,%2,%3}, {%4,%5,%6,%7}, {%8,%9}, {%0,%1,%2,%3};"
        : "+f"(c[0]), "+f"(c[1]), "+f"(c[2]), "+f"(c[3])
        : "r"(a[0]), "r"(a[1]), "r"(a[2]), "r"(a[3]), "r"(b[0]), "r"(b[1]));
}
__device__ __forceinline__ float silu_f(float x) { return x / (1.0f + expf(-x)); }

// ---------------------------------------------------------------------------
// tf32 GEMM, 512 threads, BM=BN=128, BK=16, 16 warps in 4x4 grid, 32x32 warp
// tiles. A tile: [k][m] layout (136 stride, conflict-free scalar frag reads).
// B tile: permuted into mma fragment order -> conflict-free LDS.64 frag reads.
// FUSE: B is packed [up64|gate64] per 128 cols; epilogue computes
// t = up * silu(gate) and writes 64 cols at bn/2 (ldc applies to t layout).
// Requires M%128==0, N%128==0, K%16==0.
// ---------------------------------------------------------------------------
template <bool ACC, bool FUSE>
__global__ __launch_bounds__(512) void tf32_gemm512(
    const float* __restrict__ A, const float* __restrict__ B, float* __restrict__ C,
    int K, int lda, int ldb, int ldc)
{
    __shared__ float sm[8448];
    // As(buf,k,m) = sm[buf*2176 + k*136 + m]      (2 x 16 x 136)
    // Bs(buf,s)   = sm[4352 + buf*2048 + s]       (2 x 2048), s=((ks*16+nt)*32+lane)*2+r
    // sg(r,c)     = sm[r*65 + c]                  (epilogue alias, 128x65 <= 8448)

    const int tid = threadIdx.x;
    const int bm = blockIdx.y * 128;
    const int bn = blockIdx.x * 128;
    const int w = tid >> 5, lane = tid & 31;
    const int wr = w & 3, wc = w >> 2;
    const int wm = wr * 32, wn = wc * 32;
    const int g = lane >> 2, tg = lane & 3;

    // A staging: one float4 per thread
    const int ar = tid >> 2, aq = (tid & 3) * 4;
    const float* Ap = A + (long)(bm + ar) * lda + aq;

    // B gather staging: slots s0, s0+1 ; 2 elems (r=0,1) each
    const int s0 = tid * 2;
    const float* Bpp[2][2];
#pragma unroll
    for (int i = 0; i < 2; ++i) {
        int s = s0 + i, R = s >> 5, l = s & 31;
        int ks = R >> 4, nt = R & 15, gg = l >> 2, tt = l & 3;
#pragma unroll
        for (int r = 0; r < 2; ++r)
            Bpp[i][r] = B + (long)(ks * 8 + r * 4 + tt) * ldb + bn + nt * 8 + gg;
    }

    float acc[2][4][4];
#pragma unroll
    for (int mi = 0; mi < 2; ++mi)
#pragma unroll
        for (int j = 0; j < 4; ++j)
#pragma unroll
            for (int q = 0; q < 4; ++q) acc[mi][j][q] = 0.0f;

    const int ntile = K / 16;

    // prologue
    {
        float4 av = *(const float4*)Ap;
        float bvv[2][2];
#pragma unroll
        for (int i = 0; i < 2; ++i)
#pragma unroll
            for (int r = 0; r < 2; ++r) bvv[i][r] = *Bpp[i][r];
        float* as = sm;  // buf 0
        as[(aq + 0) * 136 + ar] = to_tf32(av.x);
        as[(aq + 1) * 136 + ar] = to_tf32(av.y);
        as[(aq + 2) * 136 + ar] = to_tf32(av.z);
        as[(aq + 3) * 136 + ar] = to_tf32(av.w);
#pragma unroll
        for (int i = 0; i < 2; ++i) {
            float2 t2 = make_float2(to_tf32(bvv[i][0]), to_tf32(bvv[i][1]));
            *(float2*)&sm[4352 + (s0 + i) * 2] = t2;
        }
    }
    __syncthreads();

    int buf = 0;
    for (int t = 0; t < ntile; ++t) {
        float4 av;
        float bvv[2][2];
        const bool pf = (t + 1 < ntile);
        if (pf) {
            const int ko = (t + 1) * 16;
            av = *(const float4*)(Ap + ko);
#pragma unroll
            for (int i = 0; i < 2; ++i)
#pragma unroll
                for (int r = 0; r < 2; ++r) bvv[i][r] = *(Bpp[i][r] + (long)ko * ldb);
        }

        const float* as = sm + buf * 2176;
        const float* bs = sm + 4352 + buf * 2048;
#pragma unroll
        for (int ks_i = 0; ks_i < 2; ++ks_i) {
            const int kk = ks_i * 8;
            uint32_t af[2][4];
#pragma unroll
            for (int mi = 0; mi < 2; ++mi) {
                const int mo = wm + mi * 16;
                af[mi][0] = __float_as_uint(as[(kk + tg) * 136 + mo + g]);
                af[mi][1] = __float_as_uint(as[(kk + tg) * 136 + mo + g + 8]);
                af[mi][2] = __float_as_uint(as[(kk + tg + 4) * 136 + mo + g]);
                af[mi][3] = __float_as_uint(as[(kk + tg + 4) * 136 + mo + g + 8]);
            }
#pragma unroll
            for (int j = 0; j < 4; ++j) {
                float2 bq = *(const float2*)(bs + ((ks_i * 16 + wc * 4 + j) * 32 + lane) * 2);
                uint32_t bf[2] = { __float_as_uint(bq.x), __float_as_uint(bq.y) };
                mma_tf32(acc[0][j], af[0], bf);
                mma_tf32(acc[1][j], af[1], bf);
            }
        }

        if (pf) {
            const int nb = buf ^ 1;
            float* asw = sm + nb * 2176;
            asw[(aq + 0) * 136 + ar] = to_tf32(av.x);
            asw[(aq + 1) * 136 + ar] = to_tf32(av.y);
            asw[(aq + 2) * 136 + ar] = to_tf32(av.z);
            asw[(aq + 3) * 136 + ar] = to_tf32(av.w);
#pragma unroll
            for (int i = 0; i < 2; ++i) {
                float2 t2 = make_float2(to_tf32(bvv[i][0]), to_tf32(bvv[i][1]));
                *(float2*)&sm[4352 + nb * 2048 + (s0 + i) * 2] = t2;
            }
        }
        __syncthreads();
        buf ^= 1;
    }

    if (!FUSE) {
#pragma unroll
        for (int mi = 0; mi < 2; ++mi) {
            const int row0 = bm + wm + mi * 16 + g;
#pragma unroll
            for (int j = 0; j < 4; ++j) {
                const int col = bn + wn + j * 8 + tg * 2;
                float* p0 = C + (long)row0 * ldc + col;
                float* p1 = p0 + 8 * ldc;
                if (ACC) {
                    p0[0] += acc[mi][j][0]; p0[1] += acc[mi][j][1];
                    p1[0] += acc[mi][j][2]; p1[1] += acc[mi][j][3];
                } else {
                    p0[0] = acc[mi][j][0]; p0[1] = acc[mi][j][1];
                    p1[0] = acc[mi][j][2]; p1[1] = acc[mi][j][3];
                }
            }
        }
    } else {
        // warps wc>=2 hold gate cols (64..127); push silu through smem
        __syncthreads();   // staging buffers now dead
        if (wc >= 2) {
#pragma unroll
            for (int mi = 0; mi < 2; ++mi) {
                const int r0 = wm + mi * 16 + g;
#pragma unroll
                for (int j = 0; j < 4; ++j) {
                    const int c0 = (wn - 64) + j * 8 + tg * 2;
                    sm[r0 * 65 + c0]           = silu_f(acc[mi][j][0]);
                    sm[r0 * 65 + c0 + 1]       = silu_f(acc[mi][j][1]);
                    sm[(r0 + 8) * 65 + c0]     = silu_f(acc[mi][j][2]);
                    sm[(r0 + 8) * 65 + c0 + 1] = silu_f(acc[mi][j][3]);
                }
            }
        }
        __syncthreads();
        if (wc < 2) {
#pragma unroll
            for (int mi = 0; mi < 2; ++mi) {
                const int r0 = wm + mi * 16 + g;
#pragma unroll
                for (int j = 0; j < 4; ++j) {
                    const int c0 = wn + j * 8 + tg * 2;
                    float* p0 = C + (long)(bm + r0) * ldc + (bn >> 1) + c0;
                    float* p1 = p0 + 8 * ldc;
                    p0[0] = acc[mi][j][0] * sm[r0 * 65 + c0];
                    p0[1] = acc[mi][j][1] * sm[r0 * 65 + c0 + 1];
                    p1[0] = acc[mi][j][2] * sm[(r0 + 8) * 65 + c0];
                    p1[1] = acc[mi][j][3] * sm[(r0 + 8) * 65 + c0 + 1];
                }
            }
        }
    }
}

// ---------------------------------------------------------------------------
// Weight packing
// ---------------------------------------------------------------------------
__global__ __launch_bounds__(256) void pack_proj_kernel(
    const float* __restrict__ Wk, const float* __restrict__ Wv,
    const float* __restrict__ Wql, const float* __restrict__ Wqr,
    float* __restrict__ P)
{
    int i = blockIdx.x * 256 + threadIdx.x;     // H_DIM * 384
    int r = i / PROJ_W, c = i % PROJ_W;
    float v;
    if (c < 128)      v = Wk[r * 128 + c];
    else if (c < 256) v = Wv[r * 128 + (c - 128)];
    else if (c < 320) v = Wql[r * 64 + (c - 256)];
    else              v = Wqr[r * 64 + (c - 320)];
    P[i] = v;
}

// interleaved: per 128-col block b: [ W_up[:,64b..64b+64) | W_gate[:, same) ]
__global__ __launch_bounds__(256) void pack_ug_kernel(
    const float* __restrict__ Wu, const float* __restrict__ Wg, float* __restrict__ P)
{
    int i = blockIdx.x * 256 + threadIdx.x;     // H_DIM * 4096
    int r = i >> 12, c = i & 4095;
    int b = c >> 7, loc = c & 127;
    int src = b * 64 + (loc & 63);
    P[i] = (loc < 64) ? Wu[r * 2048 + src] : Wg[r * 2048 + src];
}

// ---------------------------------------------------------------------------
__global__ __launch_bounds__(256) void decay_kernel(
    const float* __restrict__ x, const float* __restrict__ Wd, float* __restrict__ dec)
{
    const int token = blockIdx.x * 8 + (threadIdx.x >> 5);
    const int lane = threadIdx.x & 31;
    const float* xr = x + (long)token * H_DIM;
    float s = 0.0f;
#pragma unroll 8
    for (int j = lane; j < H_DIM; j += 32) s = fmaf(xr[j], Wd[j], s);
#pragma unroll
    for (int o = 16; o; o >>= 1) s += __shfl_xor_sync(0xffffffffu, s, o);
    if (lane == 0) dec[token] = 1.0f / (1.0f + expf(-s));
}

// ---------------------------------------------------------------------------
// Chunked scan. state_{s+1} = d*state + (1-d)*write is linear in state, so:
// pass1: per chunk, A_c = prod(d), B_c = chunk-local accumulation from 0.
// pass2: serial over chunks: S_{c+1} = A_c * S_c + B_c (S_c = chunk-start state).
// pass3: per chunk, recompute with known start state and emit silu(reads).
// ---------------------------------------------------------------------------
__global__ __launch_bounds__(512) void scan_pass1(
    const float* __restrict__ proj, const float* __restrict__ decay,
    float* __restrict__ cA, float* __restrict__ cB)
{
    const int b = blockIdx.y, c = blockIdx.x;
    const int tid = threadIdx.x;
    const int m = tid & 63, n0 = (tid >> 6) * 8;
    const long base = (long)b * SEQ + c * CHUNK;

    float st[8];
#pragma unroll
    for (int j = 0; j < 8; ++j) st[j] = 0.0f;
    float a = 1.0f;

    for (int s = 0; s < CHUNK; ++s) {
        const float* row = proj + (base + s) * PROJ_W;
        float d = decay[base + s];
        float k0 = row[m], k1 = row[64 + m];
        float4 v0a = *(const float4*)(row + 128 + n0);
        float4 v0b = *(const float4*)(row + 128 + n0 + 4);
        float4 v1a = *(const float4*)(row + 192 + n0);
        float4 v1b = *(const float4*)(row + 192 + n0 + 4);
        float v0[8] = {v0a.x, v0a.y, v0a.z, v0a.w, v0b.x, v0b.y, v0b.z, v0b.w};
        float v1[8] = {v1a.x, v1a.y, v1a.z, v1a.w, v1b.x, v1b.y, v1b.z, v1b.w};
        a *= d;
        float omd = 1.0f - d;
#pragma unroll
        for (int j = 0; j < 8; ++j) {
            float wv = 0.5f * (k0 * v0[j] + k1 * v1[j]);
            st[j] = fmaf(d, st[j], omd * wv);
        }
    }

    float* out = cB + ((long)(b * NCHUNK + c) * 64 + m) * 64 + n0;
#pragma unroll
    for (int j = 0; j < 8; ++j) out[j] = st[j];
    if (tid == 0) cA[b * NCHUNK + c] = a;
}

__global__ __launch_bounds__(512) void scan_pass2(
    const float* __restrict__ init_state, const float* __restrict__ cA,
    const float* __restrict__ cB, float* __restrict__ cS)
{
    const int b = blockIdx.x;
    const int i0 = threadIdx.x * 8;   // over 4096
    float st[8];
#pragma unroll
    for (int j = 0; j < 8; ++j) st[j] = init_state[i0 + j];

    for (int c = 0; c < NCHUNK; ++c) {
        const long o = (long)(b * NCHUNK + c) * 4096 + i0;
#pragma unroll
        for (int j = 0; j < 8; ++j) cS[o + j] = st[j];
        float a = cA[b * NCHUNK + c];
#pragma unroll
        for (int j = 0; j < 8; ++j) st[j] = fmaf(a, st[j], cB[o + j]);
    }
}

__global__ __launch_bounds__(512) void scan_pass3(
    const float* __restrict__ proj, const float* __restrict__ decay,
    const float* __restrict__ cS, float* __restrict__ sr)
{
    const int b = blockIdx.z, c = blockIdx.y;
    const int n0 = blockIdx.x * 8;
    const int tid = threadIdx.x;
    const int nl = tid >> 6;
    const int m = tid & 63;
    const int n = n0 + nl;
    const int lane = tid & 31;
    const int half = (m >> 5);

    __shared__ float part[2][8][2];

    float st = cS[(long)(b * NCHUNK + c) * 4096 + m * 64 + n];
    const long base = (long)b * SEQ + c * CHUNK;

    const float* row = proj + base * PROJ_W;
    float d = decay[base];
    float k0 = row[m], k1 = row[64 + m];
    float v0 = row[128 + n], v1 = row[192 + n];
    float qlm = row[256 + m], qrn = row[320 + n];

    for (int s = 0; s < CHUNK; ++s) {
        float nd = 0.f, nk0 = 0.f, nk1 = 0.f, nv0 = 0.f, nv1 = 0.f, nql = 0.f, nqr = 0.f;
        if (s + 1 < CHUNK) {
            const float* nr = proj + (base + s + 1) * PROJ_W;
            nd = decay[base + s + 1];
            nk0 = nr[m];       nk1 = nr[64 + m];
            nv0 = nr[128 + n]; nv1 = nr[192 + n];
            nql = nr[256 + m]; nqr = nr[320 + n];
        }

        float wv = 0.5f * (k0 * v0 + k1 * v1);
        st = fmaf(d, st, (1.0f - d) * wv);

        float p = qlm * st;
#pragma unroll
        for (int o = 16; o; o >>= 1) p += __shfl_xor_sync(0xffffffffu, p, o);
        if (lane == 0) part[s & 1][nl][half] = p;
        __syncthreads();
        if (m == 0) {
            float rd = (part[s & 1][nl][0] + part[s & 1][nl][1]) * qrn;
            sr[(base + s) * M_DIM + n] = rd / (1.0f + expf(-rd));
        }

        d = nd; k0 = nk0; k1 = nk1; v0 = nv0; v1 = nv1; qlm = nql; qrn = nqr;
    }
}

// ---------------------------------------------------------------------------
extern "C" void kernel_launch(void* const* d_in, const int* in_sizes, int n_in,
                              void* d_out, int out_size)
{
    const float* x       = (const float*)d_in[0];
    const float* W_decay = (const float*)d_in[1];
    const float* W_key   = (const float*)d_in[2];
    const float* W_value = (const float*)d_in[3];
    const float* W_ql    = (const float*)d_in[4];
    const float* W_qr    = (const float*)d_in[5];
    const float* W_rec   = (const float*)d_in[6];
    const float* W_up    = (const float*)d_in[7];
    const float* W_gate  = (const float*)d_in[8];
    const float* W_down  = (const float*)d_in[9];
    const float* init_st = (const float*)d_in[10];
    float* out = (float*)d_out;

    void *p_proj, *p_dec, *p_t, *p_sr, *p_wp, *p_wug, *p_cA, *p_cB, *p_cS;
    cudaGetSymbolAddress(&p_proj, g_proj);
    cudaGetSymbolAddress(&p_dec,  g_decay);
    cudaGetSymbolAddress(&p_t,    g_t);
    cudaGetSymbolAddress(&p_sr,   g_sr);
    cudaGetSymbolAddress(&p_wp,   g_wproj);
    cudaGetSymbolAddress(&p_wug,  g_wug);
    cudaGetSymbolAddress(&p_cA,   g_cA);
    cudaGetSymbolAddress(&p_cB,   g_cB);
    cudaGetSymbolAddress(&p_cS,   g_cS);
    float* proj = (float*)p_proj;
    float* dec  = (float*)p_dec;
    float* tbuf = (float*)p_t;
    float* sr   = (float*)p_sr;
    float* wp   = (float*)p_wp;
    float* wug  = (float*)p_wug;
    float* cA   = (float*)p_cA;
    float* cB   = (float*)p_cB;
    float* cS   = (float*)p_cS;

    const dim3 b256(256), b512(512);
    const int MB = NTOK / 128;   // 64

    pack_proj_kernel<<<(H_DIM * PROJ_W) / 256, b256>>>(W_key, W_value, W_ql, W_qr, wp);
    pack_ug_kernel<<<(H_DIM * 4096) / 256, b256>>>(W_up, W_gate, wug);
    decay_kernel<<<NTOK / 8, b256>>>(x, W_decay, dec);

    // Projections: one GEMM, N=384
    tf32_gemm512<false, false><<<dim3(3, MB), b512>>>(x, wp, proj, H_DIM, H_DIM, PROJ_W, PROJ_W);

    // Chunked scan -> silu(reads)
    scan_pass1<<<dim3(NCHUNK, BATCH), b512>>>(proj, dec, cA, cB);
    scan_pass2<<<BATCH, b512>>>(init_st, cA, cB, cS);
    scan_pass3<<<dim3(8, NCHUNK, BATCH), b512>>>(proj, dec, cS, sr);

    // FFN up|gate fused with swiglu -> t
    tf32_gemm512<false, true><<<dim3(32, MB), b512>>>(x, wug, tbuf, H_DIM, H_DIM, 4096, LS_DIM);

    // out = t @ W_down
    tf32_gemm512<false, false><<<dim3(8, MB), b512>>>(tbuf, W_down, out, LS_DIM, LS_DIM, H_DIM, H_DIM);
    // out += silu(reads) @ W_rec_out
    tf32_gemm512<true, false><<<dim3(8, MB), b512>>>(sr, W_rec, out, M_DIM, M_DIM, H_DIM, H_DIM);
}

// round 4
// speedup vs baseline: 4.5694x; 1.6951x over previous
#include <cuda_runtime.h>
#include <math.h>
#include <stdint.h>

#define H_DIM   1024
#define M_DIM   64
#define LS_DIM  2048
#define BATCH   4
#define SEQ     2048
#define NTOK    8192
#define PROJ_W  384
#define CHUNK   64
#define NCHUNK  32

// Scratch (device globals)
__device__ float g_xf[(size_t)NTOK * H_DIM];         // x, A-frag-major
__device__ float g_proj[(size_t)NTOK * PROJ_W];      // natural row-major
__device__ float g_decay[NTOK];
__device__ float g_t[(size_t)NTOK * LS_DIM];         // t, A-frag-major
__device__ float g_sr[(size_t)NTOK * M_DIM];         // silu(reads), A-frag-major
__device__ float g_wp[(size_t)H_DIM * PROJ_W];       // B-frag-major packed proj weights
__device__ float g_wug[(size_t)H_DIM * 4096];        // B-frag-major packed [u64|g64]x32
__device__ float g_wdn[(size_t)LS_DIM * H_DIM];      // B-frag-major W_down
__device__ float g_wrc[(size_t)M_DIM * H_DIM];       // B-frag-major W_rec
__device__ float g_cA[BATCH * NCHUNK];
__device__ float g_cB[(size_t)BATCH * NCHUNK * 4096];
__device__ float g_cS[(size_t)BATCH * NCHUNK * 4096];

// ---------------------------------------------------------------------------
__device__ __forceinline__ float to_tf32(float x) {
    float r; asm("cvt.rna.tf32.f32 %0, %1;" : "=f"(r) : "f"(x)); return r;
}
__device__ __forceinline__ float silu_f(float x) { return x / (1.0f + expf(-x)); }
__device__ __forceinline__ void mma_tf32(float* c, const uint32_t* a, const uint32_t* b) {
    asm volatile(
        "mma.sync.aligned.m16n8k8.row.col.f32.tf32.tf32.f32 "
        "{%0,%1,%2,%3}, {%4,%5,%6,%7}, {%8,%9}, {%0,%1,%2,%3};"
        : "+f"(c[0]), "+f"(c[1]), "+f"(c[2]), "+f"(c[3])
        : "r"(a[0]), "r"(a[1]), "r"(a[2]), "r"(a[3]), "r"(b[0]), "r"(b[1]));
}

#define CP16(s, g)  asm volatile("cp.async.cg.shared.global [%0], [%1], 16;" :: "r"(s), "l"(g))
#define CPCOMMIT()  asm volatile("cp.async.commit_group;" ::: "memory")
#define CPWAIT1()   asm volatile("cp.async.wait_group 1;" ::: "memory")

// Fragment-major offsets within a 128x16 tile (2048 floats)
__device__ __forceinline__ int afrag_off(int m128, int k16) {
    int wr = m128 >> 5, mi = (m128 >> 4) & 1, h = (m128 >> 3) & 1, g = m128 & 7;
    int ks = k16 >> 3, u = (k16 >> 2) & 1, tg = k16 & 3;
    return (wr * 4 + ks * 2 + mi) * 128 + (g * 4 + tg) * 4 + h + 2 * u;
}

// ---------------------------------------------------------------------------
// tf32 tensor-core GEMM, frag-major operands, cp.async 3-stage pipeline.
// 256 threads = 8 warps (4x2), warp tile 32x64, BM=BN=128, BK=16.
// A layout: [mtile][ktile][2048 frag-major], B: [ntile][ktile][2048].
// WB: 0 = natural store, 1 = natural accumulate, 2 = fused swiglu -> A-frag-major C
// ---------------------------------------------------------------------------
template <int WB>
__global__ __launch_bounds__(256, 2) void gemm_tc(
    const float* __restrict__ A, const float* __restrict__ B, float* __restrict__ C,
    int nkt, int ldc)
{
    __shared__ float sm[12288];    // 3 stages x (2048 A + 2048 B); epilogue reuse

    const int tid = threadIdx.x;
    const int w = tid >> 5, lane = tid & 31;
    const int wr = w & 3, wc = w >> 1 >> 1;   // wc = w>>2
    const int g = lane >> 2, tg = lane & 3;

    const float* Abase = A + ((long)blockIdx.y * nkt) * 2048 + tid * 8;
    const float* Bbase = B + ((long)blockIdx.x * nkt) * 2048 + tid * 8;
    const uint32_t sbase = (uint32_t)__cvta_generic_to_shared(sm);

    float acc[2][8][4];
#pragma unroll
    for (int mi = 0; mi < 2; ++mi)
#pragma unroll
        for (int j = 0; j < 8; ++j)
#pragma unroll
            for (int q = 0; q < 4; ++q) acc[mi][j][q] = 0.0f;

    // prologue: stages 0,1
    {
        uint32_t sa = sbase + tid * 32u;
        CP16(sa, Abase); CP16(sa + 16, Abase + 4);
        CP16(sa + 8192, Bbase); CP16(sa + 8208, Bbase + 4);
        CPCOMMIT();
        sa = sbase + 16384u + tid * 32u;
        const float* ag = Abase + 2048; const float* bg = Bbase + 2048;
        CP16(sa, ag); CP16(sa + 16, ag + 4);
        CP16(sa + 8192, bg); CP16(sa + 8208, bg + 4);
        CPCOMMIT();
    }

    const int abase_f = wr * 512 + lane * 4;
    const int bbase_f = 2048 + wc * 1024 + lane * 4;

    int bufC = 0, bufI = 2;
    for (int t = 0; t < nkt; ++t) {
        CPWAIT1();
        __syncthreads();
        if (t + 2 < nkt) {
            uint32_t sa = sbase + bufI * 16384u + tid * 32u;
            const float* ag = Abase + (long)(t + 2) * 2048;
            const float* bg = Bbase + (long)(t + 2) * 2048;
            CP16(sa, ag); CP16(sa + 16, ag + 4);
            CP16(sa + 8192, bg); CP16(sa + 8208, bg + 4);
        }
        CPCOMMIT();

        const float* as = sm + bufC * 4096;
        float4 af0 = *(const float4*)(as + abase_f);          // ks0 mi0
        float4 af1 = *(const float4*)(as + abase_f + 128);    // ks0 mi1
        float4 af2 = *(const float4*)(as + abase_f + 256);    // ks1 mi0
        float4 af3 = *(const float4*)(as + abase_f + 384);    // ks1 mi1
        const float* bs = as + bbase_f;
#pragma unroll
        for (int j = 0; j < 8; ++j) {
            float4 bv = *(const float4*)(bs + j * 128);
            uint32_t b0[2] = { __float_as_uint(bv.x), __float_as_uint(bv.y) };
            uint32_t b1[2] = { __float_as_uint(bv.z), __float_as_uint(bv.w) };
            mma_tf32(acc[0][j], (const uint32_t*)&af0, b0);
            mma_tf32(acc[1][j], (const uint32_t*)&af1, b0);
            mma_tf32(acc[0][j], (const uint32_t*)&af2, b1);
            mma_tf32(acc[1][j], (const uint32_t*)&af3, b1);
        }
        bufC = (bufC == 2) ? 0 : bufC + 1;
        bufI = (bufI == 2) ? 0 : bufI + 1;
    }

    if (WB != 2) {
#pragma unroll
        for (int mi = 0; mi < 2; ++mi) {
            const int row0 = blockIdx.y * 128 + wr * 32 + mi * 16 + g;
#pragma unroll
            for (int j = 0; j < 8; ++j) {
                const int col = blockIdx.x * 128 + wc * 64 + j * 8 + tg * 2;
                float* p0 = C + (long)row0 * ldc + col;
                float* p1 = p0 + 8 * ldc;
                if (WB == 1) {
                    p0[0] += acc[mi][j][0]; p0[1] += acc[mi][j][1];
                    p1[0] += acc[mi][j][2]; p1[1] += acc[mi][j][3];
                } else {
                    p0[0] = acc[mi][j][0]; p0[1] = acc[mi][j][1];
                    p1[0] = acc[mi][j][2]; p1[1] = acc[mi][j][3];
                }
            }
        }
    } else {
        // fused swiglu: wc==1 warps hold gate cols; sg stored transposed [c][r] stride 132
        __syncthreads();
        if (wc == 1) {
#pragma unroll
            for (int mi = 0; mi < 2; ++mi) {
                const int r = wr * 32 + mi * 16 + g;
#pragma unroll
                for (int j = 0; j < 8; ++j) {
                    const int c = j * 8 + tg * 2;
                    sm[c * 132 + r]           = silu_f(acc[mi][j][0]);
                    sm[(c + 1) * 132 + r]     = silu_f(acc[mi][j][1]);
                    sm[c * 132 + r + 8]       = silu_f(acc[mi][j][2]);
                    sm[(c + 1) * 132 + r + 8] = silu_f(acc[mi][j][3]);
                }
            }
        }
        __syncthreads();
        if (wc == 0) {
            const long mtbase = (long)blockIdx.y * 128 * 2048;   // nkt_down = 128
            const int ncb = blockIdx.x * 64;
#pragma unroll
            for (int mi = 0; mi < 2; ++mi) {
                const int r = wr * 32 + mi * 16 + g;
#pragma unroll
                for (int j = 0; j < 8; ++j) {
                    const int c = j * 8 + tg * 2;
                    float t0 = acc[mi][j][0] * sm[c * 132 + r];
                    float t1 = acc[mi][j][1] * sm[(c + 1) * 132 + r];
                    float t2 = acc[mi][j][2] * sm[c * 132 + r + 8];
                    float t3 = acc[mi][j][3] * sm[(c + 1) * 132 + r + 8];
                    int n0 = ncb + c, n1 = n0 + 1;
                    C[mtbase + (long)(n0 >> 4) * 2048 + afrag_off(r, n0 & 15)]     = to_tf32(t0);
                    C[mtbase + (long)(n1 >> 4) * 2048 + afrag_off(r, n1 & 15)]     = to_tf32(t1);
                    C[mtbase + (long)(n0 >> 4) * 2048 + afrag_off(r + 8, n0 & 15)] = to_tf32(t2);
                    C[mtbase + (long)(n1 >> 4) * 2048 + afrag_off(r + 8, n1 & 15)] = to_tf32(t3);
                }
            }
        }
    }
}

// ---------------------------------------------------------------------------
// Layout packers (gather by output index), all emit tf32-rounded values
// ---------------------------------------------------------------------------
__global__ __launch_bounds__(256) void xperm_kernel(const float* __restrict__ x, float* __restrict__ out)
{
    int o = blockIdx.x * 256 + threadIdx.x;          // NTOK*H
    int mt = o >> 17, rem = o & 131071;
    int kt = rem >> 11, s = rem & 2047;
    int slab = s >> 7, lane = (s >> 2) & 31, q = s & 3;
    int wr = slab >> 2, ks = (slab >> 1) & 1, mi = slab & 1;
    int g = lane >> 2, tg = lane & 3, h = q & 1, u = q >> 1;
    int m = mt * 128 + wr * 32 + mi * 16 + h * 8 + g;
    int k = kt * 16 + ks * 8 + u * 4 + tg;
    out[o] = to_tf32(x[(long)m * H_DIM + k]);
}

__device__ __forceinline__ void bfrag_src(int o, int nkt, int& k, int& n)
{
    int per_nt = nkt << 11;
    int nt = o / per_nt, rem = o - nt * per_nt;
    int kt = rem >> 11, s = rem & 2047;
    int wc = s >> 10, j = (s >> 7) & 7, lane = (s >> 2) & 31;
    int ks = (s >> 1) & 1, r = s & 1;
    int g = lane >> 2, tg = lane & 3;
    n = nt * 128 + wc * 64 + j * 8 + g;
    k = kt * 16 + ks * 8 + r * 4 + tg;
}

__global__ __launch_bounds__(256) void pack_b_kernel(const float* __restrict__ W, float* __restrict__ out,
                                                     int N, int nkt)
{
    int o = blockIdx.x * 256 + threadIdx.x;
    int k, n; bfrag_src(o, nkt, k, n);
    out[o] = to_tf32(W[(long)k * N + n]);
}

__global__ __launch_bounds__(256) void pack_wp_kernel(
    const float* __restrict__ Wk, const float* __restrict__ Wv,
    const float* __restrict__ Wql, const float* __restrict__ Wqr, float* __restrict__ out)
{
    int o = blockIdx.x * 256 + threadIdx.x;          // H*384
    int k, n; bfrag_src(o, 64, k, n);
    float v;
    if (n < 128)      v = Wk[k * 128 + n];
    else if (n < 256) v = Wv[k * 128 + (n - 128)];
    else if (n < 320) v = Wql[k * 64 + (n - 256)];
    else              v = Wqr[k * 64 + (n - 320)];
    out[o] = to_tf32(v);
}

__global__ __launch_bounds__(256) void pack_wug_kernel(
    const float* __restrict__ Wu, const float* __restrict__ Wg, float* __restrict__ out)
{
    int o = blockIdx.x * 256 + threadIdx.x;          // H*4096
    int k, n; bfrag_src(o, 64, k, n);
    int b = n >> 7, loc = n & 127;
    int col = b * 64 + (loc & 63);
    float v = (loc < 64) ? Wu[(long)k * 2048 + col] : Wg[(long)k * 2048 + col];
    out[o] = to_tf32(v);
}

// ---------------------------------------------------------------------------
__global__ __launch_bounds__(256) void decay_kernel(
    const float* __restrict__ x, const float* __restrict__ Wd, float* __restrict__ dec)
{
    const int token = blockIdx.x * 8 + (threadIdx.x >> 5);
    const int lane = threadIdx.x & 31;
    const float* xr = x + (long)token * H_DIM;
    float s = 0.0f;
#pragma unroll 8
    for (int j = lane; j < H_DIM; j += 32) s = fmaf(xr[j], Wd[j], s);
#pragma unroll
    for (int o = 16; o; o >>= 1) s += __shfl_xor_sync(0xffffffffu, s, o);
    if (lane == 0) dec[token] = 1.0f / (1.0f + expf(-s));
}

// ---------------------------------------------------------------------------
// Chunked scan (3 passes; see round-2 derivation)
// ---------------------------------------------------------------------------
__global__ __launch_bounds__(512) void scan_pass1(
    const float* __restrict__ proj, const float* __restrict__ decay,
    float* __restrict__ cA, float* __restrict__ cB)
{
    const int b = blockIdx.y, c = blockIdx.x;
    const int tid = threadIdx.x;
    const int m = tid & 63, n0 = (tid >> 6) * 8;
    const long base = (long)b * SEQ + c * CHUNK;

    float st[8];
#pragma unroll
    for (int j = 0; j < 8; ++j) st[j] = 0.0f;
    float a = 1.0f;

    for (int s = 0; s < CHUNK; ++s) {
        const float* row = proj + (base + s) * PROJ_W;
        float d = decay[base + s];
        float k0 = row[m], k1 = row[64 + m];
        float4 v0a = *(const float4*)(row + 128 + n0);
        float4 v0b = *(const float4*)(row + 128 + n0 + 4);
        float4 v1a = *(const float4*)(row + 192 + n0);
        float4 v1b = *(const float4*)(row + 192 + n0 + 4);
        float v0[8] = {v0a.x, v0a.y, v0a.z, v0a.w, v0b.x, v0b.y, v0b.z, v0b.w};
        float v1[8] = {v1a.x, v1a.y, v1a.z, v1a.w, v1b.x, v1b.y, v1b.z, v1b.w};
        a *= d;
        float omd = 1.0f - d;
#pragma unroll
        for (int j = 0; j < 8; ++j) {
            float wv = 0.5f * (k0 * v0[j] + k1 * v1[j]);
            st[j] = fmaf(d, st[j], omd * wv);
        }
    }
    float* out = cB + ((long)(b * NCHUNK + c) * 64 + m) * 64 + n0;
#pragma unroll
    for (int j = 0; j < 8; ++j) out[j] = st[j];
    if (tid == 0) cA[b * NCHUNK + c] = a;
}

__global__ __launch_bounds__(512) void scan_pass2(
    const float* __restrict__ init_state, const float* __restrict__ cA,
    const float* __restrict__ cB, float* __restrict__ cS)
{
    const int b = blockIdx.x;
    const int i0 = threadIdx.x * 8;
    float st[8];
#pragma unroll
    for (int j = 0; j < 8; ++j) st[j] = init_state[i0 + j];
    for (int c = 0; c < NCHUNK; ++c) {
        const long o = (long)(b * NCHUNK + c) * 4096 + i0;
#pragma unroll
        for (int j = 0; j < 8; ++j) cS[o + j] = st[j];
        float a = cA[b * NCHUNK + c];
#pragma unroll
        for (int j = 0; j < 8; ++j) st[j] = fmaf(a, st[j], cB[o + j]);
    }
}

__global__ __launch_bounds__(512) void scan_pass3(
    const float* __restrict__ proj, const float* __restrict__ decay,
    const float* __restrict__ cS, float* __restrict__ sr)
{
    const int b = blockIdx.z, c = blockIdx.y;
    const int n0 = blockIdx.x * 8;
    const int tid = threadIdx.x;
    const int nl = tid >> 6;
    const int m = tid & 63;
    const int n = n0 + nl;
    const int lane = tid & 31;
    const int half = (m >> 5);

    __shared__ float part[2][8][2];

    float st = cS[(long)(b * NCHUNK + c) * 4096 + m * 64 + n];
    const long base = (long)b * SEQ + c * CHUNK;

    const float* row = proj + base * PROJ_W;
    float d = decay[base];
    float k0 = row[m], k1 = row[64 + m];
    float v0 = row[128 + n], v1 = row[192 + n];
    float qlm = row[256 + m], qrn = row[320 + n];

    for (int s = 0; s < CHUNK; ++s) {
        float nd = 0.f, nk0 = 0.f, nk1 = 0.f, nv0 = 0.f, nv1 = 0.f, nql = 0.f, nqr = 0.f;
        if (s + 1 < CHUNK) {
            const float* nr = proj + (base + s + 1) * PROJ_W;
            nd = decay[base + s + 1];
            nk0 = nr[m];       nk1 = nr[64 + m];
            nv0 = nr[128 + n]; nv1 = nr[192 + n];
            nql = nr[256 + m]; nqr = nr[320 + n];
        }
        float wv = 0.5f * (k0 * v0 + k1 * v1);
        st = fmaf(d, st, (1.0f - d) * wv);

        float p = qlm * st;
#pragma unroll
        for (int o = 16; o; o >>= 1) p += __shfl_xor_sync(0xffffffffu, p, o);
        if (lane == 0) part[s & 1][nl][half] = p;
        __syncthreads();
        if (m == 0) {
            float rd = (part[s & 1][nl][0] + part[s & 1][nl][1]) * qrn;
            // write silu(read) in A-frag-major layout (K=64 -> nkt=4)
            int token = (int)(base + s);
            int mt = token >> 7, m128 = token & 127;
            int kt = n >> 4, k16 = n & 15;
            sr[((long)(mt * 4 + kt)) * 2048 + afrag_off(m128, k16)] = to_tf32(silu_f(rd));
        }
        d = nd; k0 = nk0; k1 = nk1; v0 = nv0; v1 = nv1; qlm = nql; qrn = nqr;
    }
}

// ---------------------------------------------------------------------------
extern "C" void kernel_launch(void* const* d_in, const int* in_sizes, int n_in,
                              void* d_out, int out_size)
{
    const float* x       = (const float*)d_in[0];
    const float* W_decay = (const float*)d_in[1];
    const float* W_key   = (const float*)d_in[2];
    const float* W_value = (const float*)d_in[3];
    const float* W_ql    = (const float*)d_in[4];
    const float* W_qr    = (const float*)d_in[5];
    const float* W_rec   = (const float*)d_in[6];
    const float* W_up    = (const float*)d_in[7];
    const float* W_gate  = (const float*)d_in[8];
    const float* W_down  = (const float*)d_in[9];
    const float* init_st = (const float*)d_in[10];
    float* out = (float*)d_out;

    void *p_xf, *p_proj, *p_dec, *p_t, *p_sr, *p_wp, *p_wug, *p_wdn, *p_wrc, *p_cA, *p_cB, *p_cS;
    cudaGetSymbolAddress(&p_xf,   g_xf);
    cudaGetSymbolAddress(&p_proj, g_proj);
    cudaGetSymbolAddress(&p_dec,  g_decay);
    cudaGetSymbolAddress(&p_t,    g_t);
    cudaGetSymbolAddress(&p_sr,   g_sr);
    cudaGetSymbolAddress(&p_wp,   g_wp);
    cudaGetSymbolAddress(&p_wug,  g_wug);
    cudaGetSymbolAddress(&p_wdn,  g_wdn);
    cudaGetSymbolAddress(&p_wrc,  g_wrc);
    cudaGetSymbolAddress(&p_cA,   g_cA);
    cudaGetSymbolAddress(&p_cB,   g_cB);
    cudaGetSymbolAddress(&p_cS,   g_cS);
    float* xf   = (float*)p_xf;
    float* proj = (float*)p_proj;
    float* dec  = (float*)p_dec;
    float* tbuf = (float*)p_t;
    float* sr   = (float*)p_sr;
    float* wp   = (float*)p_wp;
    float* wug  = (float*)p_wug;
    float* wdn  = (float*)p_wdn;
    float* wrc  = (float*)p_wrc;
    float* cA   = (float*)p_cA;
    float* cB   = (float*)p_cB;
    float* cS   = (float*)p_cS;

    const dim3 b256(256), b512(512);
    const int MB = NTOK / 128;   // 64

    // Layout packs (tf32-rounded)
    xperm_kernel<<<(NTOK * H_DIM) / 256, b256>>>(x, xf);
    pack_wp_kernel<<<(H_DIM * PROJ_W) / 256, b256>>>(W_key, W_value, W_ql, W_qr, wp);
    pack_wug_kernel<<<(H_DIM * 4096) / 256, b256>>>(W_up, W_gate, wug);
    pack_b_kernel<<<(LS_DIM * H_DIM) / 256, b256>>>(W_down, wdn, H_DIM, 128);
    pack_b_kernel<<<(M_DIM * H_DIM) / 256, b256>>>(W_rec, wrc, H_DIM, 4);
    decay_kernel<<<NTOK / 8, b256>>>(x, W_decay, dec);

    // Projections: N=384
    gemm_tc<0><<<dim3(3, MB), b256>>>(xf, wp, proj, 64, PROJ_W);

    // Chunked scan -> silu(reads) (frag-major)
    scan_pass1<<<dim3(NCHUNK, BATCH), b512>>>(proj, dec, cA, cB);
    scan_pass2<<<BATCH, b512>>>(init_st, cA, cB, cS);
    scan_pass3<<<dim3(8, NCHUNK, BATCH), b512>>>(proj, dec, cS, sr);

    // FFN up|gate fused swiglu -> t (frag-major)
    gemm_tc<2><<<dim3(32, MB), b256>>>(xf, wug, tbuf, 64, 0);

    // out = t @ W_down
    gemm_tc<0><<<dim3(8, MB), b256>>>(tbuf, wdn, out, 128, H_DIM);
    // out += silu(reads) @ W_rec_out
    gemm_tc<1><<<dim3(8, MB), b256>>>(sr, wrc, out, 4, H_DIM);
}

// round 6
// speedup vs baseline: 6.8664x; 1.5027x over previous
#include <cuda_runtime.h>
#include <cuda_fp16.h>
#include <math.h>
#include <stdint.h>

#define H_DIM   1024
#define M_DIM   64
#define LS_DIM  2048
#define BATCH   4
#define SEQ     2048
#define NTOK    8192
#define PROJ_W  384
#define CHUNK   64
#define NCHUNK  32
#define CAT_NKT 66            // 64 ktiles of t (k=2048) + 2 ktiles of sr (k=64)

// -------- scratch (device globals; allocation-free rule) --------------------
__device__ __half g_xh[(size_t)NTOK * H_DIM];               // x, A-frag tiles [mt][kt][4096h]
__device__ float  g_proj[(size_t)NTOK * PROJ_W];            // natural row-major fp32
__device__ float  g_decay[NTOK];
__device__ __half g_cat[(size_t)64 * CAT_NKT * 4096];       // [t|sr] A-frag tiles
__device__ __half g_wp[(size_t)3 * 32 * 4096];              // B-frag tiles: [Wk|Wv|Wql|Wqr]
__device__ __half g_wug[(size_t)32 * 32 * 4096];            // B-frag tiles: [u64|g64] x32
__device__ __half g_wcat[(size_t)8 * CAT_NKT * 4096];       // B-frag tiles: [Wdown;Wrec]
__device__ float  g_cA[BATCH * NCHUNK];
__device__ float  g_cB[(size_t)BATCH * NCHUNK * 4096];
__device__ float  g_cS[(size_t)BATCH * NCHUNK * 4096];

// ---------------------------------------------------------------------------
__device__ __forceinline__ float silu_f(float x) { return x / (1.0f + expf(-x)); }

__device__ __forceinline__ void mma_h(float* c, uint4 a, uint32_t b0, uint32_t b1) {
    asm volatile(
        "mma.sync.aligned.m16n8k16.row.col.f32.f16.f16.f32 "
        "{%0,%1,%2,%3}, {%4,%5,%6,%7}, {%8,%9}, {%0,%1,%2,%3};"
        : "+f"(c[0]), "+f"(c[1]), "+f"(c[2]), "+f"(c[3])
        : "r"(a.x), "r"(a.y), "r"(a.z), "r"(a.w), "r"(b0), "r"(b1));
}

#define CP16(s, g)  asm volatile("cp.async.cg.shared.global [%0], [%1], 16;" :: "r"(s), "l"(g))
#define CPCOMMITG() asm volatile("cp.async.commit_group;" ::: "memory")
#define CPWAIT1()   asm volatile("cp.async.wait_group 1;" ::: "memory")

// A-frag-major half offset within a 128(m) x 32(k) tile (4096 halfs).
// m16n8k16 A frag: a0=(g,2tg+e), a1=(g+8,..), a2=(g,8+2tg+e), a3=(g+8,8+..)
__device__ __forceinline__ int ah_off(int m, int k) {
    int wr = m >> 5, mi = (m >> 4) & 1, h = (m >> 3) & 1, g = m & 7;
    int ks = k >> 4, u = (k >> 3) & 1, tg = (k >> 1) & 3, e = k & 1;
    int word = ((wr * 4 + ks * 2 + mi) * 32 + g * 4 + tg) * 4 + h + 2 * u;
    return word * 2 + e;
}

// ---------------------------------------------------------------------------
// fp16 tensor-core GEMM. 256 threads = 8 warps (4x2), warp tile 32x64.
// BM=BN=128, ktile = 32. Frag-major operands, cp.async 3-stage pipeline.
// WB 0: natural fp32 store to C (ldc). WB 1: fused swiglu -> g_cat half tiles.
// ---------------------------------------------------------------------------
template <int WB>
__global__ __launch_bounds__(256, 2) void gemm_h(
    const __half* __restrict__ A, const __half* __restrict__ B, void* __restrict__ Cv,
    int nkt, int ldc)
{
    __shared__ uint32_t sm[12288];           // 3 stages x (2048 A + 2048 B) words

    const int tid = threadIdx.x;
    const int w = tid >> 5, lane = tid & 31;
    const int wr = w & 3, wc = w >> 2;
    const int g = lane >> 2, tg = lane & 3;

    const __half* Abase = A + (size_t)blockIdx.y * nkt * 4096 + tid * 16;
    const __half* Bbase = B + (size_t)blockIdx.x * nkt * 4096 + tid * 16;
    const uint32_t sb = (uint32_t)__cvta_generic_to_shared(sm);

    float acc[2][8][4];
#pragma unroll
    for (int mi = 0; mi < 2; ++mi)
#pragma unroll
        for (int j = 0; j < 8; ++j)
#pragma unroll
            for (int q = 0; q < 4; ++q) acc[mi][j][q] = 0.0f;

    // prologue: stages 0,1
#pragma unroll
    for (int p = 0; p < 2; ++p) {
        uint32_t sa = sb + p * 16384u + tid * 32u;
        const __half* ga = Abase + (size_t)p * 4096;
        const __half* gb = Bbase + (size_t)p * 4096;
        CP16(sa, ga); CP16(sa + 16, ga + 8);
        CP16(sa + 8192, gb); CP16(sa + 8208, gb + 8);
        CPCOMMITG();
    }

    for (int t = 0; t < nkt; ++t) {
        const int s = t - (t / 3) * 3;
        CPWAIT1();
        __syncthreads();
        if (t + 2 < nkt) {
            const int s2 = (t + 2) - ((t + 2) / 3) * 3;
            uint32_t sa = sb + s2 * 16384u + tid * 32u;
            const __half* ga = Abase + (size_t)(t + 2) * 4096;
            const __half* gb = Bbase + (size_t)(t + 2) * 4096;
            CP16(sa, ga); CP16(sa + 16, ga + 8);
            CP16(sa + 8192, gb); CP16(sa + 8208, gb + 8);
        }
        CPCOMMITG();

        const uint32_t* as = sm + s * 4096;
        const uint32_t* bs = as + 2048;
#pragma unroll
        for (int ks = 0; ks < 2; ++ks) {
            uint4 af0 = *(const uint4*)(as + (wr * 4 + ks * 2 + 0) * 128 + lane * 4);
            uint4 af1 = *(const uint4*)(as + (wr * 4 + ks * 2 + 1) * 128 + lane * 4);
#pragma unroll
            for (int jp = 0; jp < 4; ++jp) {
                uint4 bf = *(const uint4*)(bs + ((ks * 2 + wc) * 4 + jp) * 128 + lane * 4);
                mma_h(acc[0][jp * 2],     af0, bf.x, bf.y);
                mma_h(acc[1][jp * 2],     af1, bf.x, bf.y);
                mma_h(acc[0][jp * 2 + 1], af0, bf.z, bf.w);
                mma_h(acc[1][jp * 2 + 1], af1, bf.z, bf.w);
            }
        }
    }

    if (WB == 0) {
        float* C = (float*)Cv;
#pragma unroll
        for (int mi = 0; mi < 2; ++mi) {
            const int row0 = blockIdx.y * 128 + wr * 32 + mi * 16 + g;
#pragma unroll
            for (int j = 0; j < 8; ++j) {
                const int col = blockIdx.x * 128 + wc * 64 + j * 8 + tg * 2;
                float* p0 = C + (size_t)row0 * ldc + col;
                float* p1 = p0 + 8 * ldc;
                p0[0] = acc[mi][j][0]; p0[1] = acc[mi][j][1];
                p1[0] = acc[mi][j][2]; p1[1] = acc[mi][j][3];
            }
        }
    } else {
        // fused swiglu: wc==1 warps hold gate; exchange silu(gate) via smem
        __syncthreads();
        float* smf = (float*)sm;               // [c][r], stride 129 (64x129 <= 12288 words? 8256 ok)
        if (wc == 1) {
#pragma unroll
            for (int mi = 0; mi < 2; ++mi) {
                const int r = wr * 32 + mi * 16 + g;
#pragma unroll
                for (int j = 0; j < 8; ++j) {
                    const int c = j * 8 + tg * 2;
                    smf[c * 129 + r]           = silu_f(acc[mi][j][0]);
                    smf[(c + 1) * 129 + r]     = silu_f(acc[mi][j][1]);
                    smf[c * 129 + r + 8]       = silu_f(acc[mi][j][2]);
                    smf[(c + 1) * 129 + r + 8] = silu_f(acc[mi][j][3]);
                }
            }
        }
        __syncthreads();
        if (wc == 0) {
            __half* Ch = (__half*)Cv;
            const size_t mtb = (size_t)blockIdx.y * CAT_NKT * 4096;
#pragma unroll
            for (int mi = 0; mi < 2; ++mi) {
                const int r = wr * 32 + mi * 16 + g;
#pragma unroll
                for (int j = 0; j < 8; ++j) {
                    const int c = j * 8 + tg * 2;
                    float t0 = acc[mi][j][0] * smf[c * 129 + r];
                    float t1 = acc[mi][j][1] * smf[(c + 1) * 129 + r];
                    float t2 = acc[mi][j][2] * smf[c * 129 + r + 8];
                    float t3 = acc[mi][j][3] * smf[(c + 1) * 129 + r + 8];
                    const int colg = blockIdx.x * 64 + c;
                    const int kt = colg >> 5, kk = colg & 31;
                    __half* tb = Ch + mtb + (size_t)kt * 4096;
                    *(__half2*)(tb + ah_off(r, kk))     = __floats2half2_rn(t0, t1);
                    *(__half2*)(tb + ah_off(r + 8, kk)) = __floats2half2_rn(t2, t3);
                }
            }
        }
    }
}

// ---------------------------------------------------------------------------
// Packers (gather by output half index)
// ---------------------------------------------------------------------------
__global__ __launch_bounds__(256) void pack_xh(const float* __restrict__ x, __half* __restrict__ out)
{
    int o = blockIdx.x * 256 + threadIdx.x;       // NTOK * H halfs
    int tile = o >> 12, hi = o & 4095;
    int wd = hi >> 1, e = hi & 1;
    int idx = wd >> 7, lane = (wd >> 2) & 31, reg = wd & 3;
    int g = lane >> 2, tg = lane & 3;
    int wr = idx >> 2, ks = (idx >> 1) & 1, mi = idx & 1, h = reg & 1, u = reg >> 1;
    int m = wr * 32 + mi * 16 + h * 8 + g;
    int k = ks * 16 + u * 8 + tg * 2 + e;
    int mt = tile >> 5, kt = tile & 31;
    out[o] = __float2half_rn(x[(size_t)(mt * 128 + m) * H_DIM + kt * 32 + k]);
}

// B-frag packer. mode 0: wp (nkt=32), 1: wug (nkt=32), 2: wcat (nkt=66)
__global__ __launch_bounds__(256) void pack_bh(
    const float* __restrict__ S0, const float* __restrict__ S1,
    const float* __restrict__ S2, const float* __restrict__ S3,
    __half* __restrict__ out, int mode, int nkt)
{
    int o = blockIdx.x * 256 + threadIdx.x;
    int tile = o >> 12, hi = o & 4095;
    int nt = tile / nkt, kt = tile - nt * nkt;
    int wd = hi >> 1, e = hi & 1;
    int idx = wd >> 7, lane = (wd >> 2) & 31, wreg = wd & 3;
    int g = lane >> 2, tg = lane & 3;
    int jp = idx & 3, t2 = idx >> 2;
    int ks = t2 >> 1, wc = t2 & 1;
    int j = jp * 2 + (wreg >> 1), r = wreg & 1;
    int nl = wc * 64 + j * 8 + g;
    int kg = kt * 32 + ks * 16 + r * 8 + tg * 2 + e;

    float v;
    if (mode == 0) {
        int n = nt * 128 + nl;
        if (n < 128)      v = S0[(size_t)kg * 128 + n];
        else if (n < 256) v = S1[(size_t)kg * 128 + (n - 128)];
        else if (n < 320) v = S2[(size_t)kg * 64 + (n - 256)];
        else              v = S3[(size_t)kg * 64 + (n - 320)];
    } else if (mode == 1) {
        int col = nt * 64 + (nl & 63);
        v = (nl < 64) ? S0[(size_t)kg * LS_DIM + col] : S1[(size_t)kg * LS_DIM + col];
    } else {
        int n = nt * 128 + nl;
        v = (kg < 2048) ? S0[(size_t)kg * H_DIM + n] : S1[(size_t)(kg - 2048) * H_DIM + n];
    }
    out[o] = __float2half_rn(v);
}

// ---------------------------------------------------------------------------
__global__ __launch_bounds__(256) void decay_kernel(
    const float* __restrict__ x, const float* __restrict__ Wd, float* __restrict__ dec)
{
    const int token = blockIdx.x * 8 + (threadIdx.x >> 5);
    const int lane = threadIdx.x & 31;
    const float* xr = x + (size_t)token * H_DIM;
    float s = 0.0f;
#pragma unroll 8
    for (int j = lane; j < H_DIM; j += 32) s = fmaf(xr[j], Wd[j], s);
#pragma unroll
    for (int o = 16; o; o >>= 1) s += __shfl_xor_sync(0xffffffffu, s, o);
    if (lane == 0) dec[token] = 1.0f / (1.0f + expf(-s));
}

// ---------------------------------------------------------------------------
// Chunked scan (3 passes; linear recurrence decomposition) — all fp32
// ---------------------------------------------------------------------------
__global__ __launch_bounds__(512) void scan_pass1(
    const float* __restrict__ proj, const float* __restrict__ decay,
    float* __restrict__ cA, float* __restrict__ cB)
{
    const int b = blockIdx.y, c = blockIdx.x;
    const int tid = threadIdx.x;
    const int m = tid & 63, n0 = (tid >> 6) * 8;
    const size_t base = (size_t)b * SEQ + c * CHUNK;

    float st[8];
#pragma unroll
    for (int j = 0; j < 8; ++j) st[j] = 0.0f;
    float a = 1.0f;

    for (int s = 0; s < CHUNK; ++s) {
        const float* row = proj + (base + s) * PROJ_W;
        float d = decay[base + s];
        float k0 = row[m], k1 = row[64 + m];
        float4 v0a = *(const float4*)(row + 128 + n0);
        float4 v0b = *(const float4*)(row + 128 + n0 + 4);
        float4 v1a = *(const float4*)(row + 192 + n0);
        float4 v1b = *(const float4*)(row + 192 + n0 + 4);
        float v0[8] = {v0a.x, v0a.y, v0a.z, v0a.w, v0b.x, v0b.y, v0b.z, v0b.w};
        float v1[8] = {v1a.x, v1a.y, v1a.z, v1a.w, v1b.x, v1b.y, v1b.z, v1b.w};
        a *= d;
        float omd = 1.0f - d;
#pragma unroll
        for (int j = 0; j < 8; ++j) {
            float wv = 0.5f * (k0 * v0[j] + k1 * v1[j]);
            st[j] = fmaf(d, st[j], omd * wv);
        }
    }
    float* o = cB + ((size_t)(b * NCHUNK + c) * 64 + m) * 64 + n0;
#pragma unroll
    for (int j = 0; j < 8; ++j) o[j] = st[j];
    if (tid == 0) cA[b * NCHUNK + c] = a;
}

__global__ __launch_bounds__(512) void scan_pass2(
    const float* __restrict__ init_state, const float* __restrict__ cA,
    const float* __restrict__ cB, float* __restrict__ cS)
{
    const int b = blockIdx.x;
    const int i0 = threadIdx.x * 8;
    float st[8];
#pragma unroll
    for (int j = 0; j < 8; ++j) st[j] = init_state[i0 + j];
    for (int c = 0; c < NCHUNK; ++c) {
        const size_t o = (size_t)(b * NCHUNK + c) * 4096 + i0;
#pragma unroll
        for (int j = 0; j < 8; ++j) cS[o + j] = st[j];
        float a = cA[b * NCHUNK + c];
#pragma unroll
        for (int j = 0; j < 8; ++j) st[j] = fmaf(a, st[j], cB[o + j]);
    }
}

__global__ __launch_bounds__(512) void scan_pass3(
    const float* __restrict__ proj, const float* __restrict__ decay,
    const float* __restrict__ cS, __half* __restrict__ cat)
{
    const int b = blockIdx.z, c = blockIdx.y;
    const int n0 = blockIdx.x * 8;
    const int tid = threadIdx.x;
    const int nl = tid >> 6;
    const int m = tid & 63;
    const int n = n0 + nl;
    const int lane = tid & 31;
    const int half_ = (m >> 5);

    __shared__ float part[2][8][2];

    float st = cS[(size_t)(b * NCHUNK + c) * 4096 + m * 64 + n];
    const size_t base = (size_t)b * SEQ + c * CHUNK;

    const float* row = proj + base * PROJ_W;
    float d = decay[base];
    float k0 = row[m], k1 = row[64 + m];
    float v0 = row[128 + n], v1 = row[192 + n];
    float qlm = row[256 + m], qrn = row[320 + n];

    for (int s = 0; s < CHUNK; ++s) {
        float nd = 0.f, nk0 = 0.f, nk1 = 0.f, nv0 = 0.f, nv1 = 0.f, nql = 0.f, nqr = 0.f;
        if (s + 1 < CHUNK) {
            const float* nr = proj + (base + s + 1) * PROJ_W;
            nd = decay[base + s + 1];
            nk0 = nr[m];       nk1 = nr[64 + m];
            nv0 = nr[128 + n]; nv1 = nr[192 + n];
            nql = nr[256 + m]; nqr = nr[320 + n];
        }
        float wv = 0.5f * (k0 * v0 + k1 * v1);
        st = fmaf(d, st, (1.0f - d) * wv);

        float p = qlm * st;
#pragma unroll
        for (int o = 16; o; o >>= 1) p += __shfl_xor_sync(0xffffffffu, p, o);
        if (lane == 0) part[s & 1][nl][half_] = p;
        __syncthreads();
        if (m == 0) {
            float rd = (part[s & 1][nl][0] + part[s & 1][nl][1]) * qrn;
            int token = (int)(base + s);
            int mt = token >> 7, r = token & 127;
            int kt = 64 + (n >> 5), kk = n & 31;
            cat[((size_t)mt * CAT_NKT + kt) * 4096 + ah_off(r, kk)] = __float2half_rn(silu_f(rd));
        }
        d = nd; k0 = nk0; k1 = nk1; v0 = nv0; v1 = nv1; qlm = nql; qrn = nqr;
    }
}

// ---------------------------------------------------------------------------
extern "C" void kernel_launch(void* const* d_in, const int* in_sizes, int n_in,
                              void* d_out, int out_size)
{
    const float* x       = (const float*)d_in[0];
    const float* W_decay = (const float*)d_in[1];
    const float* W_key   = (const float*)d_in[2];
    const float* W_value = (const float*)d_in[3];
    const float* W_ql    = (const float*)d_in[4];
    const float* W_qr    = (const float*)d_in[5];
    const float* W_rec   = (const float*)d_in[6];
    const float* W_up    = (const float*)d_in[7];
    const float* W_gate  = (const float*)d_in[8];
    const float* W_down  = (const float*)d_in[9];
    const float* init_st = (const float*)d_in[10];
    float* out = (float*)d_out;

    void *p_xh, *p_proj, *p_dec, *p_cat, *p_wp, *p_wug, *p_wcat, *p_cA, *p_cB, *p_cS;
    cudaGetSymbolAddress(&p_xh,   g_xh);
    cudaGetSymbolAddress(&p_proj, g_proj);
    cudaGetSymbolAddress(&p_dec,  g_decay);
    cudaGetSymbolAddress(&p_cat,  g_cat);
    cudaGetSymbolAddress(&p_wp,   g_wp);
    cudaGetSymbolAddress(&p_wug,  g_wug);
    cudaGetSymbolAddress(&p_wcat, g_wcat);
    cudaGetSymbolAddress(&p_cA,   g_cA);
    cudaGetSymbolAddress(&p_cB,   g_cB);
    cudaGetSymbolAddress(&p_cS,   g_cS);
    __half* xh   = (__half*)p_xh;
    float*  proj = (float*)p_proj;
    float*  dec  = (float*)p_dec;
    __half* cat  = (__half*)p_cat;
    __half* wp   = (__half*)p_wp;
    __half* wug  = (__half*)p_wug;
    __half* wcat = (__half*)p_wcat;
    float*  cA   = (float*)p_cA;
    float*  cB   = (float*)p_cB;
    float*  cS   = (float*)p_cS;

    const dim3 b256(256), b512(512);

    // packs
    pack_xh<<<(NTOK * H_DIM) / 256, b256>>>(x, xh);
    pack_bh<<<(3 * 32 * 4096) / 256, b256>>>(W_key, W_value, W_ql, W_qr, wp, 0, 32);
    pack_bh<<<(32 * 32 * 4096) / 256, b256>>>(W_up, W_gate, nullptr, nullptr, wug, 1, 32);
    pack_bh<<<(8 * CAT_NKT * 4096) / 256, b256>>>(W_down, W_rec, nullptr, nullptr, wcat, 2, CAT_NKT);
    decay_kernel<<<NTOK / 8, b256>>>(x, W_decay, dec);

    // projections: N=384 natural fp32 -> g_proj
    gemm_h<0><<<dim3(3, 64), b256>>>(xh, wp, proj, 32, PROJ_W);

    // chunked scan -> silu(reads) into cat ktiles 64..65
    scan_pass1<<<dim3(NCHUNK, BATCH), b512>>>(proj, dec, cA, cB);
    scan_pass2<<<BATCH, b512>>>(init_st, cA, cB, cS);
    scan_pass3<<<dim3(8, NCHUNK, BATCH), b512>>>(proj, dec, cS, cat);

    // FFN up|gate + fused swiglu -> cat ktiles 0..63
    gemm_h<1><<<dim3(32, 64), b256>>>(xh, wug, cat, 32, 0);

    // out = [t|sr] @ [W_down;W_rec]  (single GEMM, K=2112)
    gemm_h<0><<<dim3(8, 64), b256>>>(cat, wcat, out, CAT_NKT, H_DIM);
}